// round 13
// baseline (speedup 1.0000x reference)
#include <cuda_runtime.h>
#include <cstdint>
#include <math.h>

// ---------------- problem constants ----------------
#define TOKENS 32768      // B*N
#define CDIM   384        // C
#define KDIM   384
#define NH     8
#define HD     48
#define NSEQ   4096
#define BATCH  8
#define NSPLIT 16         // attn n-splits

// ---------------- scratch (static device globals; no allocs) ----------------
__device__ float g_v       [(size_t)TOKENS * CDIM];   // 48 MB
__device__ __align__(16) char g_codes_i8[(size_t)TOKENS * CDIM];   // 12 MB (+-1/0)
__device__ float g_attn    [NSPLIT * 64 * HD * HD];   // n-split partials
__device__ float g_attn_red[64 * HD * HD];            // reduced attn
__device__ unsigned g_attn_cnt[64];                   // last-block counters (zero-init)
__device__ float g_mid     [(size_t)TOKENS * CDIM];   // 48 MB
__device__ float g_w2      [CDIM * CDIM];             // hash-fused qk weight

// ---------------- f32x2 helpers ----------------
__device__ __forceinline__ unsigned long long pack2(float x, float y) {
    unsigned long long r;
    asm("mov.b64 %0, {%1, %2};" : "=l"(r) : "f"(x), "f"(y));
    return r;
}
__device__ __forceinline__ void ffma2(unsigned long long &acc,
                                      unsigned long long a,
                                      unsigned long long b) {
    asm("fma.rn.f32x2 %0, %1, %2, %0;" : "+l"(acc) : "l"(a), "l"(b));
}
__device__ __forceinline__ float lo32(unsigned long long v) {
    return __uint_as_float((unsigned)(v & 0xffffffffull));
}
__device__ __forceinline__ float hi32(unsigned long long v) {
    return __uint_as_float((unsigned)(v >> 32));
}

// ---------------- W2[h*48+f][c] = sum_d hash[h,f,d] * w_qk[h*48+d][c] ----------
__global__ void __launch_bounds__(128) fuse_w2(
    const float* __restrict__ wqk, const float* __restrict__ hashp, int row0)
{
    int row = row0 + blockIdx.x;     // (= h*48+f)
    int h = row / HD;
    __shared__ float hr[HD];
    int tid = threadIdx.x;
    if (tid < HD) hr[tid] = hashp[row * HD + tid];
    __syncthreads();
    for (int c = tid; c < CDIM; c += 128) {
        float s = 0.f;
#pragma unroll
        for (int d = 0; d < HD; d++)
            s = fmaf(hr[d], wqk[(size_t)(h * HD + d) * CDIM + c], s);
        g_w2[(size_t)row * CDIM + c] = s;
    }
}

// ---------------- fp32 FFMA2 SGEMM v4: conflict-free 32x64 warp tiles ----------
#define BM  128
#define BN  128
#define BK2 16
#define NST (KDIM / BK2)   // 24

__device__ __forceinline__ void sgemm_v4(
    const float* __restrict__ A, const float* __restrict__ Bm,
    float* __restrict__ C, char* __restrict__ C8,
    const float* __restrict__ bias, int mTile, int nTile, int do_sign)
{
    __shared__ __align__(16) float As[2][BK2][BM];
    __shared__ __align__(16) float Bs[2][BK2][BN];

    int tid  = threadIdx.x;
    int lane = tid & 31, wid = tid >> 5;
    int aRow = tid >> 1;
    int aCol = (tid & 1) << 3;

    // warp tile 32(m) x 64(n); lane micro-tile 8m x (4+4)n
    int warp_m = wid & 3, warp_n = wid >> 2;
    int g_m = lane >> 3, g_n = lane & 7;
    int tm   = warp_m * 32 + g_m * 8;
    int tn_a = warp_n * 64 + g_n * 4;
    int tn_b = tn_a + 32;

    const float* Ap = A  + (size_t)(mTile * BM + aRow) * KDIM + aCol;
    const float* Bp = Bm + (size_t)(nTile * BN + aRow) * KDIM + aCol;

    unsigned long long acc[8][4];
#pragma unroll
    for (int i = 0; i < 8; i++)
#pragma unroll
        for (int j = 0; j < 4; j++) acc[i][j] = 0ull;

    {
        float4 a0 = *(const float4*)Ap;
        float4 a1 = *(const float4*)(Ap + 4);
        float4 b0 = *(const float4*)Bp;
        float4 b1 = *(const float4*)(Bp + 4);
        As[0][aCol + 0][aRow] = a0.x; As[0][aCol + 1][aRow] = a0.y;
        As[0][aCol + 2][aRow] = a0.z; As[0][aCol + 3][aRow] = a0.w;
        As[0][aCol + 4][aRow] = a1.x; As[0][aCol + 5][aRow] = a1.y;
        As[0][aCol + 6][aRow] = a1.z; As[0][aCol + 7][aRow] = a1.w;
        Bs[0][aCol + 0][aRow] = b0.x; Bs[0][aCol + 1][aRow] = b0.y;
        Bs[0][aCol + 2][aRow] = b0.z; Bs[0][aCol + 3][aRow] = b0.w;
        Bs[0][aCol + 4][aRow] = b1.x; Bs[0][aCol + 5][aRow] = b1.y;
        Bs[0][aCol + 6][aRow] = b1.z; Bs[0][aCol + 7][aRow] = b1.w;
    }
    __syncthreads();

#pragma unroll 1
    for (int s = 0; s < NST; s++) {
        int buf = s & 1;
        float4 na0, na1, nb0, nb1;
        if (s + 1 < NST) {
            const float* Ap2 = Ap + (s + 1) * BK2;
            const float* Bp2 = Bp + (s + 1) * BK2;
            na0 = *(const float4*)Ap2;
            na1 = *(const float4*)(Ap2 + 4);
            nb0 = *(const float4*)Bp2;
            nb1 = *(const float4*)(Bp2 + 4);
        }
#pragma unroll
        for (int k = 0; k < BK2; k++) {
            float4 x0 = *(const float4*)&As[buf][k][tm];
            float4 x1 = *(const float4*)&As[buf][k][tm + 4];
            ulonglong2 ya = *(const ulonglong2*)&Bs[buf][k][tn_a];
            ulonglong2 yb = *(const ulonglong2*)&Bs[buf][k][tn_b];
            float aa[8] = {x0.x, x0.y, x0.z, x0.w, x1.x, x1.y, x1.z, x1.w};
#pragma unroll
            for (int i = 0; i < 8; i++) {
                unsigned long long ap = pack2(aa[i], aa[i]);
                ffma2(acc[i][0], ap, ya.x);
                ffma2(acc[i][1], ap, ya.y);
                ffma2(acc[i][2], ap, yb.x);
                ffma2(acc[i][3], ap, yb.y);
            }
        }
        if (s + 1 < NST) {
            int nb = buf ^ 1;
            As[nb][aCol + 0][aRow] = na0.x; As[nb][aCol + 1][aRow] = na0.y;
            As[nb][aCol + 2][aRow] = na0.z; As[nb][aCol + 3][aRow] = na0.w;
            As[nb][aCol + 4][aRow] = na1.x; As[nb][aCol + 5][aRow] = na1.y;
            As[nb][aCol + 6][aRow] = na1.z; As[nb][aCol + 7][aRow] = na1.w;
            Bs[nb][aCol + 0][aRow] = nb0.x; Bs[nb][aCol + 1][aRow] = nb0.y;
            Bs[nb][aCol + 2][aRow] = nb0.z; Bs[nb][aCol + 3][aRow] = nb0.w;
            Bs[nb][aCol + 4][aRow] = nb1.x; Bs[nb][aCol + 5][aRow] = nb1.y;
            Bs[nb][aCol + 6][aRow] = nb1.z; Bs[nb][aCol + 7][aRow] = nb1.w;
            __syncthreads();
        }
    }

#pragma unroll
    for (int i = 0; i < 8; i++) {
        size_t rowbase = (size_t)(mTile * BM + tm + i) * CDIM + nTile * BN;
        float ra[4], rb[4];
        ra[0] = lo32(acc[i][0]); ra[1] = hi32(acc[i][0]);
        ra[2] = lo32(acc[i][1]); ra[3] = hi32(acc[i][1]);
        rb[0] = lo32(acc[i][2]); rb[1] = hi32(acc[i][2]);
        rb[2] = lo32(acc[i][3]); rb[3] = hi32(acc[i][3]);
        if (do_sign) {
            unsigned ua = 0, ub = 0;
#pragma unroll
            for (int j = 0; j < 4; j++) {
                int ca = (ra[j] > 0.f) ? 1 : ((ra[j] < 0.f) ? -1 : 0);
                int cb = (rb[j] > 0.f) ? 1 : ((rb[j] < 0.f) ? -1 : 0);
                ua |= ((unsigned)(unsigned char)ca) << (8 * j);
                ub |= ((unsigned)(unsigned char)cb) << (8 * j);
            }
            *(unsigned*)&C8[rowbase + tn_a] = ua;
            *(unsigned*)&C8[rowbase + tn_b] = ub;
        } else {
            if (bias) {
#pragma unroll
                for (int j = 0; j < 4; j++) {
                    ra[j] += bias[nTile * BN + tn_a + j];
                    rb[j] += bias[nTile * BN + tn_b + j];
                }
            }
            *(float4*)&C[rowbase + tn_a] = make_float4(ra[0], ra[1], ra[2], ra[3]);
            *(float4*)&C[rowbase + tn_b] = make_float4(rb[0], rb[1], rb[2], rb[3]);
        }
    }
}

// codes (sign->int8) + v GEMMs in one launch: y<3 -> codes, y>=3 -> v
__global__ void __launch_bounds__(256, 2) sgemm_cv(
    const float* __restrict__ x, const float* __restrict__ wv)
{
    int ny = blockIdx.y;
    if (ny < 3) sgemm_v4(x, g_w2, nullptr, g_codes_i8, nullptr, blockIdx.x, ny, 1);
    else        sgemm_v4(x, wv, g_v, nullptr, nullptr, blockIdx.x, ny - 3, 0);
}

__global__ void __launch_bounds__(256, 2) sgemm_proj(
    const float* __restrict__ wproj, const float* __restrict__ bias,
    float* __restrict__ out)
{
    sgemm_v4(g_mid, wproj, out, nullptr, bias, blockIdx.x, blockIdx.y, 0);
}

// ---------------- attn[f,d] = sum_n codes[n,f] * v[n,d] + fused reduce --------
// grid (64, NSPLIT), 192 threads (48 f x 4 d-quarters of 12), f32x2 FMAs.
__global__ void __launch_bounds__(192) attn_kernel()
{
    int bh = blockIdx.x;
    int split = blockIdx.y;
    int b = bh >> 3, h = bh & 7;
    __shared__ __align__(16) float cs[32][HD];
    __shared__ __align__(16) float vs[32][HD];
    __shared__ unsigned s_last;
    int tid = threadIdx.x;
    int f  = tid % HD;
    int d0 = (tid / HD) * 12;
    unsigned long long acc[6];
#pragma unroll
    for (int j = 0; j < 6; j++) acc[j] = 0ull;

    int nbase = split * (NSEQ / NSPLIT);
    for (int t0 = 0; t0 < NSEQ / NSPLIT; t0 += 32) {
        __syncthreads();
        for (int i = tid; i < 32 * HD / 4; i += 192) {
            int t = (i * 4) / HD, d = (i * 4) % HD;
            size_t row = (size_t)(b * NSEQ + nbase + t0 + t) * CDIM + h * HD + d;
            char4 c4 = *(const char4*)&g_codes_i8[row];
            *(float4*)&cs[t][d] =
                make_float4((float)c4.x, (float)c4.y, (float)c4.z, (float)c4.w);
            *(float4*)&vs[t][d] = *(const float4*)&g_v[row];
        }
        __syncthreads();
#pragma unroll
        for (int t = 0; t < 32; t++) {
            float cf = cs[t][f];
            unsigned long long p = pack2(cf, cf);
            const ulonglong2* vp = (const ulonglong2*)&vs[t][d0];
            ulonglong2 v0 = vp[0], v1 = vp[1], v2 = vp[2];
            ffma2(acc[0], p, v0.x); ffma2(acc[1], p, v0.y);
            ffma2(acc[2], p, v1.x); ffma2(acc[3], p, v1.y);
            ffma2(acc[4], p, v2.x); ffma2(acc[5], p, v2.y);
        }
    }
    size_t base = ((size_t)split * 64 + bh) * (HD * HD) + (size_t)f * HD + d0;
    *(float4*)&g_attn[base] =
        make_float4(lo32(acc[0]), hi32(acc[0]), lo32(acc[1]), hi32(acc[1]));
    *(float4*)&g_attn[base + 4] =
        make_float4(lo32(acc[2]), hi32(acc[2]), lo32(acc[3]), hi32(acc[3]));
    *(float4*)&g_attn[base + 8] =
        make_float4(lo32(acc[4]), hi32(acc[4]), lo32(acc[5]), hi32(acc[5]));

    // last-block-per-bh reduction (deterministic fixed-order sum)
    __threadfence();
    if (tid == 0)
        s_last = (atomicAdd(&g_attn_cnt[bh], 1u) == NSPLIT - 1) ? 1u : 0u;
    __syncthreads();
    if (s_last) {
        for (int i = tid; i < HD * HD; i += 192) {
            float s = 0.f;
#pragma unroll
            for (int p = 0; p < NSPLIT; p++)
                s += g_attn[((size_t)p * 64 + bh) * (HD * HD) + i];
            g_attn_red[(size_t)bh * (HD * HD) + i] = s;
        }
        if (tid == 0) g_attn_cnt[bh] = 0;   // reset for next graph replay
    }
}

// ---------------- epilogue: 0.5v + (1/(48pi)) codes@attn, L2-norm, + dconv ------
// 64 tokens/block, 2 tokens per thread x 12 dims, f32x2 math; ~27KB smem
// -> 7 blocks/SM. grid (64, 64), block 128.
#define VSTR 52
__global__ void __launch_bounds__(128, 7) outmid_kernel(const float* __restrict__ wdc)
{
    int bh = blockIdx.x;
    int b = bh >> 3, h = bh & 7;
    int t0 = blockIdx.y * 64;
    __shared__ __align__(16) float attn_s[HD * HD];
    __shared__ __align__(16) float v_s[72 * VSTR];
    __shared__ __align__(16) unsigned codes_u[64][12];
    __shared__ float wc[9];
    int tid = threadIdx.x;

    for (int i = tid; i < (HD * HD) / 4; i += 128)
        ((float4*)attn_s)[i] = ((const float4*)&g_attn_red[(size_t)bh * HD * HD])[i];
    if (tid < 9) wc[tid] = wdc[h * 9 + tid];
    for (int i = tid; i < 72 * 12; i += 128) {
        int tt = i / 12, d4 = i % 12;
        int n = t0 + tt - 4;
        float4 vv = make_float4(0.f, 0.f, 0.f, 0.f);
        if (n >= 0 && n < NSEQ)
            vv = *(const float4*)&g_v[((size_t)b * NSEQ + n) * CDIM + h * HD + d4 * 4];
        *(float4*)&v_s[tt * VSTR + d4 * 4] = vv;
    }
    for (int i = tid; i < 64 * 12; i += 128) {
        int t = i / 12, w = i % 12;
        codes_u[t][w] = *(const unsigned*)
            &g_codes_i8[((size_t)b * NSEQ + t0 + t) * CDIM + h * HD + w * 4];
    }
    __syncthreads();

    int tq = tid >> 2;           // token pair: tokens {tq, tq+32}
    int r  = tid & 3;            // dim quarter: r*12
    const float cscale = 1.f / (48.f * 3.14159265358979323846f);

    unsigned long long acc[2][6];
#pragma unroll
    for (int i = 0; i < 2; i++)
#pragma unroll
        for (int j = 0; j < 6; j++) acc[i][j] = 0ull;

#pragma unroll 1
    for (int w = 0; w < 12; w++) {
        unsigned u0 = codes_u[tq][w];
        unsigned u1 = codes_u[tq + 32][w];
#pragma unroll
        for (int j = 0; j < 4; j++) {
            const ulonglong2* ap =
                (const ulonglong2*)&attn_s[(w * 4 + j) * HD + r * 12];
            ulonglong2 a0 = ap[0], a1 = ap[1], a2 = ap[2];
            float c0 = (float)((int)(u0 << (24 - 8 * j)) >> 24);
            float c1 = (float)((int)(u1 << (24 - 8 * j)) >> 24);
            unsigned long long p0 = pack2(c0, c0);
            unsigned long long p1 = pack2(c1, c1);
            ffma2(acc[0][0], p0, a0.x); ffma2(acc[0][1], p0, a0.y);
            ffma2(acc[0][2], p0, a1.x); ffma2(acc[0][3], p0, a1.y);
            ffma2(acc[0][4], p0, a2.x); ffma2(acc[0][5], p0, a2.y);
            ffma2(acc[1][0], p1, a0.x); ffma2(acc[1][1], p1, a0.y);
            ffma2(acc[1][2], p1, a1.x); ffma2(acc[1][3], p1, a1.y);
            ffma2(acc[1][4], p1, a2.x); ffma2(acc[1][5], p1, a2.y);
        }
    }

#pragma unroll
    for (int i = 0; i < 2; i++) {
        int t = tq + i * 32;
        int n = t0 + t;
        size_t row = ((size_t)b * NSEQ + n) * CDIM + h * HD;
        const float* vrow = &v_s[(t + 4) * VSTR + r * 12];

        float val[12];
        float ss = 0.f;
#pragma unroll
        for (int d2 = 0; d2 < 6; d2++) {
            float lo = lo32(acc[i][d2]);
            float hi = hi32(acc[i][d2]);
            float v0 = 0.5f * vrow[d2 * 2]     + cscale * lo;
            float v1 = 0.5f * vrow[d2 * 2 + 1] + cscale * hi;
            val[d2 * 2] = v0; val[d2 * 2 + 1] = v1;
            ss = fmaf(v0, v0, ss);
            ss = fmaf(v1, v1, ss);
        }
        ss += __shfl_xor_sync(0xffffffffu, ss, 1);
        ss += __shfl_xor_sync(0xffffffffu, ss, 2);
        float rn = 1.0f / sqrtf(ss);

        unsigned long long dv[6];
#pragma unroll
        for (int j = 0; j < 6; j++) dv[j] = 0ull;
#pragma unroll
        for (int k = 0; k < 9; k++) {
            const ulonglong2* vp =
                (const ulonglong2*)&v_s[(t + k) * VSTR + r * 12];
            ulonglong2 b0 = vp[0], b1 = vp[1], b2 = vp[2];
            unsigned long long wk = pack2(wc[k], wc[k]);
            ffma2(dv[0], wk, b0.x); ffma2(dv[1], wk, b0.y);
            ffma2(dv[2], wk, b1.x); ffma2(dv[3], wk, b1.y);
            ffma2(dv[4], wk, b2.x); ffma2(dv[5], wk, b2.y);
        }

        float o[12];
#pragma unroll
        for (int d2 = 0; d2 < 6; d2++) {
            o[d2 * 2]     = val[d2 * 2]     * rn + lo32(dv[d2]);
            o[d2 * 2 + 1] = val[d2 * 2 + 1] * rn + hi32(dv[d2]);
        }
        *(float4*)&g_mid[row + r * 12]     = make_float4(o[0], o[1], o[2], o[3]);
        *(float4*)&g_mid[row + r * 12 + 4] = make_float4(o[4], o[5], o[6], o[7]);
        *(float4*)&g_mid[row + r * 12 + 8] = make_float4(o[8], o[9], o[10], o[11]);
    }
}

// ---------------- launch ----------------
extern "C" void kernel_launch(void* const* d_in, const int* in_sizes, int n_in,
                              void* d_out, int out_size)
{
    const float* x      = (const float*)d_in[0];
    const float* w_qk   = (const float*)d_in[1];
    const float* w_v    = (const float*)d_in[2];
    const float* w_proj = (const float*)d_in[3];
    const float* b_proj = (const float*)d_in[4];
    const float* hashp  = (const float*)d_in[5];
    const float* w_dc   = (const float*)d_in[6];
    float* out = (float*)d_out;
    (void)in_sizes; (void)n_in; (void)out_size;

    // 2 fuse launches so attn_kernel sits at profile slot #4
    fuse_w2      <<<192, 128>>>(w_qk, hashp, 0);
    fuse_w2      <<<192, 128>>>(w_qk, hashp, 192);
    sgemm_cv     <<<dim3(256, 6), 256>>>(x, w_v);
    attn_kernel  <<<dim3(64, NSPLIT), 192>>>();
    outmid_kernel<<<dim3(64, 64), 128>>>(w_dc);
    sgemm_proj   <<<dim3(256, 3), 256>>>(w_proj, b_proj, out);
}

// round 14
// speedup vs baseline: 1.0512x; 1.0512x over previous
#include <cuda_runtime.h>
#include <cstdint>
#include <math.h>

// ---------------- problem constants ----------------
#define TOKENS 32768      // B*N
#define CDIM   384        // C
#define KDIM   384
#define NH     8
#define HD     48
#define NSEQ   4096
#define BATCH  8
#define NSPLIT 16         // attn n-splits

// ---------------- scratch (static device globals; no allocs) ----------------
__device__ float g_v       [(size_t)TOKENS * CDIM];   // 48 MB
__device__ __align__(16) char g_codes_i8[(size_t)TOKENS * CDIM];   // 12 MB (+-1/0)
__device__ float g_attn    [NSPLIT * 64 * HD * HD];   // n-split partials
__device__ float g_attn_red[64 * HD * HD];            // reduced attn
__device__ unsigned g_attn_cnt[64];                   // last-block counters (zero-init)
__device__ float g_mid     [(size_t)TOKENS * CDIM];   // 48 MB
__device__ float g_w2      [CDIM * CDIM];             // hash-fused qk weight

// ---------------- f32x2 helpers ----------------
__device__ __forceinline__ unsigned long long pack2(float x, float y) {
    unsigned long long r;
    asm("mov.b64 %0, {%1, %2};" : "=l"(r) : "f"(x), "f"(y));
    return r;
}
__device__ __forceinline__ void ffma2(unsigned long long &acc,
                                      unsigned long long a,
                                      unsigned long long b) {
    asm("fma.rn.f32x2 %0, %1, %2, %0;" : "+l"(acc) : "l"(a), "l"(b));
}
__device__ __forceinline__ float lo32(unsigned long long v) {
    return __uint_as_float((unsigned)(v & 0xffffffffull));
}
__device__ __forceinline__ float hi32(unsigned long long v) {
    return __uint_as_float((unsigned)(v >> 32));
}

// ---------------- W2[h*48+f][c] = sum_d hash[h,f,d] * w_qk[h*48+d][c] ----------
__global__ void __launch_bounds__(128) fuse_w2(
    const float* __restrict__ wqk, const float* __restrict__ hashp, int row0)
{
    int row = row0 + blockIdx.x;     // (= h*48+f)
    int h = row / HD;
    __shared__ float hr[HD];
    int tid = threadIdx.x;
    if (tid < HD) hr[tid] = hashp[row * HD + tid];
    __syncthreads();
    for (int c = tid; c < CDIM; c += 128) {
        float s = 0.f;
#pragma unroll
        for (int d = 0; d < HD; d++)
            s = fmaf(hr[d], wqk[(size_t)(h * HD + d) * CDIM + c], s);
        g_w2[(size_t)row * CDIM + c] = s;
    }
}

// ---------------- fp32 FFMA2 SGEMM v4: conflict-free 32x64 warp tiles ----------
#define BM  128
#define BN  128
#define BK2 16
#define NST (KDIM / BK2)   // 24

__device__ __forceinline__ void sgemm_v4(
    const float* __restrict__ A, const float* __restrict__ Bm,
    float* __restrict__ C, char* __restrict__ C8,
    const float* __restrict__ bias, int mTile, int nTile, int do_sign)
{
    __shared__ __align__(16) float As[2][BK2][BM];
    __shared__ __align__(16) float Bs[2][BK2][BN];

    int tid  = threadIdx.x;
    int lane = tid & 31, wid = tid >> 5;
    int aRow = tid >> 1;
    int aCol = (tid & 1) << 3;

    // warp tile 32(m) x 64(n); lane micro-tile 8m x (4+4)n
    int warp_m = wid & 3, warp_n = wid >> 2;
    int g_m = lane >> 3, g_n = lane & 7;
    int tm   = warp_m * 32 + g_m * 8;
    int tn_a = warp_n * 64 + g_n * 4;
    int tn_b = tn_a + 32;

    const float* Ap = A  + (size_t)(mTile * BM + aRow) * KDIM + aCol;
    const float* Bp = Bm + (size_t)(nTile * BN + aRow) * KDIM + aCol;

    unsigned long long acc[8][4];
#pragma unroll
    for (int i = 0; i < 8; i++)
#pragma unroll
        for (int j = 0; j < 4; j++) acc[i][j] = 0ull;

    {
        float4 a0 = *(const float4*)Ap;
        float4 a1 = *(const float4*)(Ap + 4);
        float4 b0 = *(const float4*)Bp;
        float4 b1 = *(const float4*)(Bp + 4);
        As[0][aCol + 0][aRow] = a0.x; As[0][aCol + 1][aRow] = a0.y;
        As[0][aCol + 2][aRow] = a0.z; As[0][aCol + 3][aRow] = a0.w;
        As[0][aCol + 4][aRow] = a1.x; As[0][aCol + 5][aRow] = a1.y;
        As[0][aCol + 6][aRow] = a1.z; As[0][aCol + 7][aRow] = a1.w;
        Bs[0][aCol + 0][aRow] = b0.x; Bs[0][aCol + 1][aRow] = b0.y;
        Bs[0][aCol + 2][aRow] = b0.z; Bs[0][aCol + 3][aRow] = b0.w;
        Bs[0][aCol + 4][aRow] = b1.x; Bs[0][aCol + 5][aRow] = b1.y;
        Bs[0][aCol + 6][aRow] = b1.z; Bs[0][aCol + 7][aRow] = b1.w;
    }
    __syncthreads();

#pragma unroll 1
    for (int s = 0; s < NST; s++) {
        int buf = s & 1;
        float4 na0, na1, nb0, nb1;
        if (s + 1 < NST) {
            const float* Ap2 = Ap + (s + 1) * BK2;
            const float* Bp2 = Bp + (s + 1) * BK2;
            na0 = *(const float4*)Ap2;
            na1 = *(const float4*)(Ap2 + 4);
            nb0 = *(const float4*)Bp2;
            nb1 = *(const float4*)(Bp2 + 4);
        }
#pragma unroll
        for (int k = 0; k < BK2; k++) {
            float4 x0 = *(const float4*)&As[buf][k][tm];
            float4 x1 = *(const float4*)&As[buf][k][tm + 4];
            ulonglong2 ya = *(const ulonglong2*)&Bs[buf][k][tn_a];
            ulonglong2 yb = *(const ulonglong2*)&Bs[buf][k][tn_b];
            float aa[8] = {x0.x, x0.y, x0.z, x0.w, x1.x, x1.y, x1.z, x1.w};
#pragma unroll
            for (int i = 0; i < 8; i++) {
                unsigned long long ap = pack2(aa[i], aa[i]);
                ffma2(acc[i][0], ap, ya.x);
                ffma2(acc[i][1], ap, ya.y);
                ffma2(acc[i][2], ap, yb.x);
                ffma2(acc[i][3], ap, yb.y);
            }
        }
        if (s + 1 < NST) {
            int nb = buf ^ 1;
            As[nb][aCol + 0][aRow] = na0.x; As[nb][aCol + 1][aRow] = na0.y;
            As[nb][aCol + 2][aRow] = na0.z; As[nb][aCol + 3][aRow] = na0.w;
            As[nb][aCol + 4][aRow] = na1.x; As[nb][aCol + 5][aRow] = na1.y;
            As[nb][aCol + 6][aRow] = na1.z; As[nb][aCol + 7][aRow] = na1.w;
            Bs[nb][aCol + 0][aRow] = nb0.x; Bs[nb][aCol + 1][aRow] = nb0.y;
            Bs[nb][aCol + 2][aRow] = nb0.z; Bs[nb][aCol + 3][aRow] = nb0.w;
            Bs[nb][aCol + 4][aRow] = nb1.x; Bs[nb][aCol + 5][aRow] = nb1.y;
            Bs[nb][aCol + 6][aRow] = nb1.z; Bs[nb][aCol + 7][aRow] = nb1.w;
            __syncthreads();
        }
    }

#pragma unroll
    for (int i = 0; i < 8; i++) {
        size_t rowbase = (size_t)(mTile * BM + tm + i) * CDIM + nTile * BN;
        float ra[4], rb[4];
        ra[0] = lo32(acc[i][0]); ra[1] = hi32(acc[i][0]);
        ra[2] = lo32(acc[i][1]); ra[3] = hi32(acc[i][1]);
        rb[0] = lo32(acc[i][2]); rb[1] = hi32(acc[i][2]);
        rb[2] = lo32(acc[i][3]); rb[3] = hi32(acc[i][3]);
        if (do_sign) {
            unsigned ua = 0, ub = 0;
#pragma unroll
            for (int j = 0; j < 4; j++) {
                int ca = (ra[j] > 0.f) ? 1 : ((ra[j] < 0.f) ? -1 : 0);
                int cb = (rb[j] > 0.f) ? 1 : ((rb[j] < 0.f) ? -1 : 0);
                ua |= ((unsigned)(unsigned char)ca) << (8 * j);
                ub |= ((unsigned)(unsigned char)cb) << (8 * j);
            }
            *(unsigned*)&C8[rowbase + tn_a] = ua;
            *(unsigned*)&C8[rowbase + tn_b] = ub;
        } else {
            if (bias) {
#pragma unroll
                for (int j = 0; j < 4; j++) {
                    ra[j] += bias[nTile * BN + tn_a + j];
                    rb[j] += bias[nTile * BN + tn_b + j];
                }
            }
            *(float4*)&C[rowbase + tn_a] = make_float4(ra[0], ra[1], ra[2], ra[3]);
            *(float4*)&C[rowbase + tn_b] = make_float4(rb[0], rb[1], rb[2], rb[3]);
        }
    }
}

// codes (sign->int8) + v GEMMs in one launch: y<3 -> codes, y>=3 -> v
__global__ void __launch_bounds__(256, 2) sgemm_cv(
    const float* __restrict__ x, const float* __restrict__ wv)
{
    int ny = blockIdx.y;
    if (ny < 3) sgemm_v4(x, g_w2, nullptr, g_codes_i8, nullptr, blockIdx.x, ny, 1);
    else        sgemm_v4(x, wv, g_v, nullptr, nullptr, blockIdx.x, ny - 3, 0);
}

__global__ void __launch_bounds__(256, 2) sgemm_proj(
    const float* __restrict__ wproj, const float* __restrict__ bias,
    float* __restrict__ out)
{
    sgemm_v4(g_mid, wproj, out, nullptr, bias, blockIdx.x, blockIdx.y, 0);
}

// ---------------- attn[f,d] = sum_n codes[n,f] * v[n,d] + fused reduce --------
// grid (64, NSPLIT), 96 threads: 24 f-pairs x 4 d-quarters, f32x2 FMAs.
// Per token step: 1 LDS.64 + 3 LDS.128 feed 12 FFMA2.
__global__ void __launch_bounds__(96) attn_kernel()
{
    int bh = blockIdx.x;
    int split = blockIdx.y;
    int b = bh >> 3, h = bh & 7;
    __shared__ __align__(16) float cs[32][HD];
    __shared__ __align__(16) float vs[32][HD];
    __shared__ unsigned s_last;
    int tid = threadIdx.x;
    int fp = tid % 24;            // f-pair: covers f = 2*fp, 2*fp+1
    int d0 = (tid / 24) * 12;     // dim quarter
    unsigned long long acc[2][6];
#pragma unroll
    for (int i = 0; i < 2; i++)
#pragma unroll
        for (int j = 0; j < 6; j++) acc[i][j] = 0ull;

    int nbase = split * (NSEQ / NSPLIT);
    for (int t0 = 0; t0 < NSEQ / NSPLIT; t0 += 32) {
        __syncthreads();
        for (int i = tid; i < 32 * HD / 4; i += 96) {
            int t = (i * 4) / HD, d = (i * 4) % HD;
            size_t row = (size_t)(b * NSEQ + nbase + t0 + t) * CDIM + h * HD + d;
            char4 c4 = *(const char4*)&g_codes_i8[row];
            *(float4*)&cs[t][d] =
                make_float4((float)c4.x, (float)c4.y, (float)c4.z, (float)c4.w);
            *(float4*)&vs[t][d] = *(const float4*)&g_v[row];
        }
        __syncthreads();
#pragma unroll
        for (int t = 0; t < 32; t++) {
            float2 cf2 = *(const float2*)&cs[t][fp * 2];
            unsigned long long p0 = pack2(cf2.x, cf2.x);
            unsigned long long p1 = pack2(cf2.y, cf2.y);
            const ulonglong2* vp = (const ulonglong2*)&vs[t][d0];
            ulonglong2 v0 = vp[0], v1 = vp[1], v2 = vp[2];
            ffma2(acc[0][0], p0, v0.x); ffma2(acc[0][1], p0, v0.y);
            ffma2(acc[0][2], p0, v1.x); ffma2(acc[0][3], p0, v1.y);
            ffma2(acc[0][4], p0, v2.x); ffma2(acc[0][5], p0, v2.y);
            ffma2(acc[1][0], p1, v0.x); ffma2(acc[1][1], p1, v0.y);
            ffma2(acc[1][2], p1, v1.x); ffma2(acc[1][3], p1, v1.y);
            ffma2(acc[1][4], p1, v2.x); ffma2(acc[1][5], p1, v2.y);
        }
    }
#pragma unroll
    for (int i = 0; i < 2; i++) {
        int f = fp * 2 + i;
        size_t base = ((size_t)split * 64 + bh) * (HD * HD) + (size_t)f * HD + d0;
        *(float4*)&g_attn[base] =
            make_float4(lo32(acc[i][0]), hi32(acc[i][0]), lo32(acc[i][1]), hi32(acc[i][1]));
        *(float4*)&g_attn[base + 4] =
            make_float4(lo32(acc[i][2]), hi32(acc[i][2]), lo32(acc[i][3]), hi32(acc[i][3]));
        *(float4*)&g_attn[base + 8] =
            make_float4(lo32(acc[i][4]), hi32(acc[i][4]), lo32(acc[i][5]), hi32(acc[i][5]));
    }

    // last-block-per-bh reduction (deterministic fixed-order sum)
    __threadfence();
    if (tid == 0)
        s_last = (atomicAdd(&g_attn_cnt[bh], 1u) == NSPLIT - 1) ? 1u : 0u;
    __syncthreads();
    if (s_last) {
        for (int i = tid; i < HD * HD; i += 96) {
            float s = 0.f;
#pragma unroll
            for (int p = 0; p < NSPLIT; p++)
                s += g_attn[((size_t)p * 64 + bh) * (HD * HD) + i];
            g_attn_red[(size_t)bh * (HD * HD) + i] = s;
        }
        if (tid == 0) g_attn_cnt[bh] = 0;   // reset for next graph replay
    }
}

// ---------------- epilogue: 0.5v + (1/(48pi)) codes@attn, L2-norm, + dconv ------
// 128 tokens/block, 4 tokens per thread x 12 dims, f32x2 math (R12 config).
// grid (64, 32), block 128, 5 blocks/SM.
#define VSTR 52
__global__ void __launch_bounds__(128, 5) outmid_kernel(const float* __restrict__ wdc)
{
    int bh = blockIdx.x;
    int b = bh >> 3, h = bh & 7;
    int t0 = blockIdx.y * 128;
    __shared__ __align__(16) float attn_s[HD * HD];
    __shared__ __align__(16) float v_s[136 * VSTR];
    __shared__ __align__(16) unsigned codes_u[128][12];
    __shared__ float wc[9];
    int tid = threadIdx.x;

    for (int i = tid; i < (HD * HD) / 4; i += 128)
        ((float4*)attn_s)[i] = ((const float4*)&g_attn_red[(size_t)bh * HD * HD])[i];
    if (tid < 9) wc[tid] = wdc[h * 9 + tid];
    for (int i = tid; i < 136 * 12; i += 128) {
        int tt = i / 12, d4 = i % 12;
        int n = t0 + tt - 4;
        float4 vv = make_float4(0.f, 0.f, 0.f, 0.f);
        if (n >= 0 && n < NSEQ)
            vv = *(const float4*)&g_v[((size_t)b * NSEQ + n) * CDIM + h * HD + d4 * 4];
        *(float4*)&v_s[tt * VSTR + d4 * 4] = vv;
    }
    for (int i = tid; i < 128 * 12; i += 128) {
        int t = i / 12, w = i % 12;
        codes_u[t][w] = *(const unsigned*)
            &g_codes_i8[((size_t)b * NSEQ + t0 + t) * CDIM + h * HD + w * 4];
    }
    __syncthreads();

    int tq = tid >> 2;           // token group: tokens {tq, tq+32, tq+64, tq+96}
    int r  = tid & 3;            // dim quarter: r*12
    const float cscale = 1.f / (48.f * 3.14159265358979323846f);

    unsigned long long acc[4][6];
#pragma unroll
    for (int i = 0; i < 4; i++)
#pragma unroll
        for (int j = 0; j < 6; j++) acc[i][j] = 0ull;

#pragma unroll 1
    for (int w = 0; w < 12; w++) {
        unsigned u0 = codes_u[tq][w];
        unsigned u1 = codes_u[tq + 32][w];
        unsigned u2 = codes_u[tq + 64][w];
        unsigned u3 = codes_u[tq + 96][w];
#pragma unroll
        for (int j = 0; j < 4; j++) {
            const ulonglong2* ap =
                (const ulonglong2*)&attn_s[(w * 4 + j) * HD + r * 12];
            ulonglong2 a0 = ap[0], a1 = ap[1], a2 = ap[2];
            float c0 = (float)((int)(u0 << (24 - 8 * j)) >> 24);
            float c1 = (float)((int)(u1 << (24 - 8 * j)) >> 24);
            float c2 = (float)((int)(u2 << (24 - 8 * j)) >> 24);
            float c3 = (float)((int)(u3 << (24 - 8 * j)) >> 24);
            unsigned long long p0 = pack2(c0, c0);
            unsigned long long p1 = pack2(c1, c1);
            unsigned long long p2 = pack2(c2, c2);
            unsigned long long p3 = pack2(c3, c3);
            ffma2(acc[0][0], p0, a0.x); ffma2(acc[0][1], p0, a0.y);
            ffma2(acc[0][2], p0, a1.x); ffma2(acc[0][3], p0, a1.y);
            ffma2(acc[0][4], p0, a2.x); ffma2(acc[0][5], p0, a2.y);
            ffma2(acc[1][0], p1, a0.x); ffma2(acc[1][1], p1, a0.y);
            ffma2(acc[1][2], p1, a1.x); ffma2(acc[1][3], p1, a1.y);
            ffma2(acc[1][4], p1, a2.x); ffma2(acc[1][5], p1, a2.y);
            ffma2(acc[2][0], p2, a0.x); ffma2(acc[2][1], p2, a0.y);
            ffma2(acc[2][2], p2, a1.x); ffma2(acc[2][3], p2, a1.y);
            ffma2(acc[2][4], p2, a2.x); ffma2(acc[2][5], p2, a2.y);
            ffma2(acc[3][0], p3, a0.x); ffma2(acc[3][1], p3, a0.y);
            ffma2(acc[3][2], p3, a1.x); ffma2(acc[3][3], p3, a1.y);
            ffma2(acc[3][4], p3, a2.x); ffma2(acc[3][5], p3, a2.y);
        }
    }

#pragma unroll
    for (int i = 0; i < 4; i++) {
        int t = tq + i * 32;
        int n = t0 + t;
        size_t row = ((size_t)b * NSEQ + n) * CDIM + h * HD;
        const float* vrow = &v_s[(t + 4) * VSTR + r * 12];

        float val[12];
        float ss = 0.f;
#pragma unroll
        for (int d2 = 0; d2 < 6; d2++) {
            float lo = lo32(acc[i][d2]);
            float hi = hi32(acc[i][d2]);
            float v0 = 0.5f * vrow[d2 * 2]     + cscale * lo;
            float v1 = 0.5f * vrow[d2 * 2 + 1] + cscale * hi;
            val[d2 * 2] = v0; val[d2 * 2 + 1] = v1;
            ss = fmaf(v0, v0, ss);
            ss = fmaf(v1, v1, ss);
        }
        ss += __shfl_xor_sync(0xffffffffu, ss, 1);
        ss += __shfl_xor_sync(0xffffffffu, ss, 2);
        float rn = 1.0f / sqrtf(ss);

        unsigned long long dv[6];
#pragma unroll
        for (int j = 0; j < 6; j++) dv[j] = 0ull;
#pragma unroll
        for (int k = 0; k < 9; k++) {
            const ulonglong2* vp =
                (const ulonglong2*)&v_s[(t + k) * VSTR + r * 12];
            ulonglong2 b0 = vp[0], b1 = vp[1], b2 = vp[2];
            unsigned long long wk = pack2(wc[k], wc[k]);
            ffma2(dv[0], wk, b0.x); ffma2(dv[1], wk, b0.y);
            ffma2(dv[2], wk, b1.x); ffma2(dv[3], wk, b1.y);
            ffma2(dv[4], wk, b2.x); ffma2(dv[5], wk, b2.y);
        }

        float o[12];
#pragma unroll
        for (int d2 = 0; d2 < 6; d2++) {
            o[d2 * 2]     = val[d2 * 2]     * rn + lo32(dv[d2]);
            o[d2 * 2 + 1] = val[d2 * 2 + 1] * rn + hi32(dv[d2]);
        }
        *(float4*)&g_mid[row + r * 12]     = make_float4(o[0], o[1], o[2], o[3]);
        *(float4*)&g_mid[row + r * 12 + 4] = make_float4(o[4], o[5], o[6], o[7]);
        *(float4*)&g_mid[row + r * 12 + 8] = make_float4(o[8], o[9], o[10], o[11]);
    }
}

// ---------------- launch ----------------
extern "C" void kernel_launch(void* const* d_in, const int* in_sizes, int n_in,
                              void* d_out, int out_size)
{
    const float* x      = (const float*)d_in[0];
    const float* w_qk   = (const float*)d_in[1];
    const float* w_v    = (const float*)d_in[2];
    const float* w_proj = (const float*)d_in[3];
    const float* b_proj = (const float*)d_in[4];
    const float* hashp  = (const float*)d_in[5];
    const float* w_dc   = (const float*)d_in[6];
    float* out = (float*)d_out;
    (void)in_sizes; (void)n_in; (void)out_size;

    fuse_w2      <<<384, 128>>>(w_qk, hashp, 0);
    sgemm_cv     <<<dim3(256, 6), 256>>>(x, w_v);
    attn_kernel  <<<dim3(64, NSPLIT), 96>>>();
    outmid_kernel<<<dim3(64, 32), 128>>>(w_dc);        // profile slot #4
    sgemm_proj   <<<dim3(256, 3), 256>>>(w_proj, b_proj, out);
}